// round 10
// baseline (speedup 1.0000x reference)
#include <cuda_runtime.h>
#include <cuda_pipeline.h>
#include <math.h>
#include <float.h>

// MultiScaleDynamicFusionGate — GB300 sm_103a — R10
//  A) stats kernel unchanged from R9 (83.5us, ~82% of practical HBM BW):
//     296 blocks single-wave, 2368 warps, contiguous chunk partition,
//     continuous 2-stage cp.async pipeline per warp.
//  B) gate kernel rebuilt: 128 blocks, each warp loops over 8 groups, so
//     weight staging is paid 128x not 1024x (R9's B kernel burned 29us on
//     per-block staging latency for 8 groups of work).

#define L_DIM 1024
#define N_ROWS 65536            // B*H*L
#define N_CHUNKS (N_ROWS * 2)   // (row, tensor) pairs, 4KB each
#define GRID_A 296
#define WARPS_A (GRID_A * 8)    // 2368

#define GRID_B 128
#define GROUPS_PER_WARP 8       // 8192 groups / (128*8 warps)

__device__ __align__(16) float g_stats[N_ROWS * 8]; // [row][s1,std1,mx1,mn1,s2,std2,mx2,mn2]

extern __shared__ float stageA[];       // [8 warps][2 stages][1024 floats] = 64KB

// ---------------------------------------------------------------- Kernel A
__global__ __launch_bounds__(256) void stats_kernel(
    const float* __restrict__ a1, const float* __restrict__ a2)
{
    const int w    = threadIdx.x >> 5;
    const int lane = threadIdx.x & 31;

    const long long gw = (long long)blockIdx.x * 8 + w;          // 0..2367
    const int c0 = (int)(((long long)N_CHUNKS * gw)       / WARPS_A);
    const int c1 = (int)(((long long)N_CHUNKS * (gw + 1)) / WARPS_A);
    const int n  = c1 - c0;

    float* stg = stageA + w * 2048;     // two 1024-float stages

    const float invL  = 1.0f / (float)L_DIM;
    const float invN1 = 1.0f / (float)(L_DIM - 1);

    #define ISSUE_CHUNK(i_)                                                     \
    do {                                                                        \
        int c_ = c0 + (i_);                                                     \
        const float* base_ = (c_ & 1) ? a2 : a1;                                \
        const float4* s4_ = (const float4*)(base_ + (long long)(c_ >> 1) * L_DIM); \
        float4* d4_ = (float4*)(stg + ((i_) & 1) * 1024);                       \
        _Pragma("unroll")                                                       \
        for (int k_ = 0; k_ < 8; k_++)                                          \
            __pipeline_memcpy_async(&d4_[lane + 32 * k_], &s4_[lane + 32 * k_], 16); \
    } while (0)

    if (n > 0) { ISSUE_CHUNK(0); }
    __pipeline_commit();

    for (int i = 0; i < n; i++) {
        if (i + 1 < n) { ISSUE_CHUNK(i + 1); }
        __pipeline_commit();            // always commit -> constant wait count
        __pipeline_wait_prior(1);       // chunk i complete; chunk i+1 in flight

        const float4* d4 = (const float4*)(stg + (i & 1) * 1024);
        float sa = 0.f, sb = 0.f, qa = 0.f, qb = 0.f;
        float mx = -FLT_MAX, mn = FLT_MAX;
        #pragma unroll
        for (int k = 0; k < 8; k++) {
            float4 v = d4[lane + 32 * k];
            if (k & 1) { sb += (v.x + v.y) + (v.z + v.w);
                         qb += (v.x * v.x + v.y * v.y) + (v.z * v.z + v.w * v.w); }
            else       { sa += (v.x + v.y) + (v.z + v.w);
                         qa += (v.x * v.x + v.y * v.y) + (v.z * v.z + v.w * v.w); }
            mx = fmaxf(mx, fmaxf(fmaxf(v.x, v.y), fmaxf(v.z, v.w)));
            mn = fminf(mn, fminf(fminf(v.x, v.y), fminf(v.z, v.w)));
        }

        float s = sa + sb, q = qa + qb;
        #pragma unroll
        for (int off = 16; off > 0; off >>= 1) {
            s  += __shfl_xor_sync(0xffffffffu, s, off);
            q  += __shfl_xor_sync(0xffffffffu, q, off);
            mx  = fmaxf(mx, __shfl_xor_sync(0xffffffffu, mx, off));
            mn  = fminf(mn, __shfl_xor_sync(0xffffffffu, mn, off));
        }
        if (lane == 0) {
            int c   = c0 + i;
            int row = c >> 1;
            float sd = sqrtf(fmaxf(0.f, (q - s * s * invL) * invN1));
            float4 st = make_float4(s, sd, mx, mn);
            *(float4*)(g_stats + (long long)row * 8 + (c & 1) * 4) = st;
        }
    }
    #undef ISSUE_CHUNK
}

// ---------------------------------------------------------------- Kernel B
__global__ __launch_bounds__(256) void gate_kernel(
    const float* __restrict__ W1, const float* __restrict__ b1,
    const float* __restrict__ W2, const float* __restrict__ b2,
    const float* __restrict__ W3, const float* __restrict__ b3,
    const float* __restrict__ sw, float* __restrict__ out)
{
    __shared__ __align__(16) float rs[8][64];   // [warp][row*8+stat]
    __shared__ float shW1T[3][8][32];    // [s][f][o]
    __shared__ float shB1[3][32];
    __shared__ float shW2T[3][32][16];   // [s][f][o]
    __shared__ float shB2[3][16];
    __shared__ float shW3[3][16];
    __shared__ float shB3[3];
    __shared__ float shSW[3];

    const int tid  = threadIdx.x;
    const int w    = tid >> 5;
    const int lane = tid & 31;

    for (int idx = tid; idx < 768; idx += 256) {          // W1 [3][32][8]
        int s = idx >> 8, rem = idx & 255;
        shW1T[s][rem & 7][rem >> 3] = W1[idx];
    }
    for (int idx = tid; idx < 1536; idx += 256) {         // W2 [3][16][32]
        int s = idx >> 9, rem = idx & 511;
        shW2T[s][rem & 31][rem >> 5] = W2[idx];
    }
    if (tid < 96)                 ((float*)shB1)[tid] = b1[tid];
    else if (tid < 144)           ((float*)shB2)[tid - 96]  = b2[tid - 96];
    else if (tid < 192)           ((float*)shW3)[tid - 144] = W3[tid - 144];
    else if (tid < 195)           ((float*)shB3)[tid - 192] = b3[tid - 192];
    else if (tid >= 200 && tid < 203) shSW[tid - 200] = sw[tid - 200];
    __syncthreads();

    const float invL = 1.0f / (float)L_DIM;

    float w0, w1g, w2g;
    {
        float t0 = shSW[0], t1 = shSW[1], t2 = shSW[2];
        float m  = fmaxf(t0, fmaxf(t1, t2));
        float e0 = __expf(t0 - m), e1 = __expf(t1 - m), e2 = __expf(t2 - m);
        float inv = 1.0f / (e0 + e1 + e2);
        w0 = e0 * inv; w1g = e1 * inv; w2g = e2 * inv;   // ws=2, ws=4, ws=8
    }

    const int gw = blockIdx.x * 8 + w;    // global warp id, 0..1023

    for (int it = 0; it < GROUPS_PER_WARP; it++) {
        const int group = gw * GROUPS_PER_WARP + it;      // 0..8191
        const long long row0 = (long long)group * 8;

        // Stage this group's 64 stats floats (L2-hot) into shared.
        if (lane < 16)
            ((float4*)&rs[w][0])[lane] = ((const float4*)(g_stats + row0 * 8))[lane];
        __syncwarp();

        float acc = 0.f;

        #pragma unroll
        for (int wi = 0; wi < 7; wi++) {
            int s, ws, r0;
            float wgt;
            if (wi == 0)      { s = 2; ws = 8; r0 = 0;            wgt = w2g; }
            else if (wi < 3)  { s = 1; ws = 4; r0 = (wi - 1) * 4; wgt = w1g; }
            else              { s = 0; ws = 2; r0 = (wi - 3) * 2; wgt = w0;  }

            const float invws = 1.0f / (float)ws;

            float g[8];
            {
                float sm1 = 0.f, sd1 = 0.f, sx1 = 0.f, sn1 = 0.f;
                float sm2 = 0.f, sd2 = 0.f, sx2 = 0.f, sn2 = 0.f;
                #pragma unroll
                for (int r = 0; r < 8; r++) {
                    if (r >= r0 && r < r0 + ws) {
                        sm1 += rs[w][r * 8 + 0]; sd1 += rs[w][r * 8 + 1];
                        sx1 += rs[w][r * 8 + 2]; sn1 += rs[w][r * 8 + 3];
                        sm2 += rs[w][r * 8 + 4]; sd2 += rs[w][r * 8 + 5];
                        sx2 += rs[w][r * 8 + 6]; sn2 += rs[w][r * 8 + 7];
                    }
                }
                g[0] = sm1 * invL * invws; g[1] = sd1 * invws;
                g[2] = sx1 * invws;        g[3] = sn1 * invws;
                g[4] = sm2 * invL * invws; g[5] = sd2 * invws;
                g[6] = sx2 * invws;        g[7] = sn2 * invws;
            }

            float h1;
            {
                float v = shB1[s][lane];
                #pragma unroll
                for (int f = 0; f < 8; f++) v = fmaf(shW1T[s][f][lane], g[f], v);
                h1 = fmaxf(v, 0.f);
            }
            float h2;
            {
                const int oo = lane & 15;
                float v = shB2[s][oo];
                #pragma unroll
                for (int f = 0; f < 32; f++)
                    v = fmaf(shW2T[s][f][oo], __shfl_sync(0xffffffffu, h1, f), v);
                h2 = fmaxf(v, 0.f);
            }
            {
                float part = (lane < 16) ? shW3[s][lane] * h2 : 0.f;
                #pragma unroll
                for (int off = 16; off > 0; off >>= 1)
                    part += __shfl_xor_sync(0xffffffffu, part, off);
                float z = __shfl_sync(0xffffffffu, part, 0) + shB3[s];
                float alpha = 1.0f / (1.0f + __expf(-z));
                if (lane >= r0 && lane < r0 + ws)
                    acc = fmaf(wgt, alpha, acc);
            }
        }

        if (lane < 8)
            out[row0 + lane] = acc;
        __syncwarp();
    }
}

extern "C" void kernel_launch(void* const* d_in, const int* in_sizes, int n_in,
                              void* d_out, int out_size) {
    const float* a1 = (const float*)d_in[0];
    const float* a2 = (const float*)d_in[1];
    const float* W1 = (const float*)d_in[2];
    const float* b1 = (const float*)d_in[3];
    const float* W2 = (const float*)d_in[4];
    const float* b2 = (const float*)d_in[5];
    const float* W3 = (const float*)d_in[6];
    const float* b3 = (const float*)d_in[7];
    const float* sw = (const float*)d_in[8];
    float* out = (float*)d_out;

    const int dyn_smem = 8 * 2 * 1024 * (int)sizeof(float);   // 64KB
    cudaFuncSetAttribute(stats_kernel,
                         cudaFuncAttributeMaxDynamicSharedMemorySize, dyn_smem);

    stats_kernel<<<GRID_A, 256, dyn_smem>>>(a1, a2);
    gate_kernel<<<GRID_B, 256>>>(W1, b1, W2, b2, W3, b3, sw, out);
}

// round 11
// speedup vs baseline: 1.1688x; 1.1688x over previous
#include <cuda_runtime.h>
#include <cuda_pipeline.h>
#include <math.h>
#include <float.h>

// MultiScaleDynamicFusionGate — GB300 sm_103a — R11
// Single kernel = R9's balanced single-wave streaming stats + inline MLP.
// 296 blocks (one wave), 2368 warps; groups (8 rows = 16 x 4KB chunks) are
// partitioned contiguously and GROUP-ALIGNED across warps (3 or 4 each,
// ~1.3% per-SM imbalance). Continuous 2-stage cp.async pipeline per warp;
// after a group's last chunk the warp runs its 7-window MLP inline while
// the next group's first chunk is already in flight. No scratch, no 2nd
// kernel (R9/R10 showed any standalone gate kernel costs ~30us on latency).

#define L_DIM 1024
#define N_ROWS 65536            // B*H*L
#define N_GROUPS 8192
#define GRID_A 296
#define WARPS_A (GRID_A * 8)    // 2368

extern __shared__ float stageA[];       // [8 warps][2 stages][1024 floats] = 64KB

__global__ __launch_bounds__(256) void msdfg_kernel(
    const float* __restrict__ a1, const float* __restrict__ a2,
    const float* __restrict__ W1, const float* __restrict__ b1,
    const float* __restrict__ W2, const float* __restrict__ b2,
    const float* __restrict__ W3, const float* __restrict__ b3,
    const float* __restrict__ sw, float* __restrict__ out)
{
    __shared__ __align__(16) float rs[8][64];   // [warp][localrow*8+stat]
    __shared__ float shW1T[3][8][32];    // [s][f][o]
    __shared__ float shB1[3][32];
    __shared__ float shW2T[3][32][16];   // [s][f][o]
    __shared__ float shB2[3][16];
    __shared__ float shW3[3][16];
    __shared__ float shB3[3];
    __shared__ float shSW[3];

    const int tid  = threadIdx.x;
    const int w    = tid >> 5;
    const int lane = tid & 31;

    // ---- One-time weight staging ----
    for (int idx = tid; idx < 768; idx += 256) {          // W1 [3][32][8]
        int s = idx >> 8, rem = idx & 255;
        shW1T[s][rem & 7][rem >> 3] = W1[idx];
    }
    for (int idx = tid; idx < 1536; idx += 256) {         // W2 [3][16][32]
        int s = idx >> 9, rem = idx & 511;
        shW2T[s][rem & 31][rem >> 5] = W2[idx];
    }
    if (tid < 96)                 ((float*)shB1)[tid] = b1[tid];
    else if (tid < 144)           ((float*)shB2)[tid - 96]  = b2[tid - 96];
    else if (tid < 192)           ((float*)shW3)[tid - 144] = W3[tid - 144];
    else if (tid < 195)           ((float*)shB3)[tid - 192] = b3[tid - 192];
    else if (tid >= 200 && tid < 203) shSW[tid - 200] = sw[tid - 200];
    __syncthreads();

    // ---- Softmax over scale_weights (registers, per warp) ----
    float w0, w1g, w2g;
    {
        float t0 = shSW[0], t1 = shSW[1], t2 = shSW[2];
        float m  = fmaxf(t0, fmaxf(t1, t2));
        float e0 = __expf(t0 - m), e1 = __expf(t1 - m), e2 = __expf(t2 - m);
        float inv = 1.0f / (e0 + e1 + e2);
        w0 = e0 * inv; w1g = e1 * inv; w2g = e2 * inv;   // ws=2, ws=4, ws=8
    }

    // ---- Group-aligned contiguous partition ----
    const long long gw = (long long)blockIdx.x * 8 + w;  // 0..2367
    const int g0 = (int)(((long long)N_GROUPS * gw)       / WARPS_A);
    const int g1 = (int)(((long long)N_GROUPS * (gw + 1)) / WARPS_A);
    const int c0 = g0 * 16;
    const int n  = (g1 - g0) * 16;      // 48 or 64 chunks

    float* stg = stageA + w * 2048;     // two 1024-float stages

    const float invL  = 1.0f / (float)L_DIM;
    const float invN1 = 1.0f / (float)(L_DIM - 1);

    // chunk c: global row = c>>1, tensor = c&1, group = c>>4
    #define ISSUE_CHUNK(i_)                                                     \
    do {                                                                        \
        int c_ = c0 + (i_);                                                     \
        const float* base_ = (c_ & 1) ? a2 : a1;                                \
        const float4* s4_ = (const float4*)(base_ + (long long)(c_ >> 1) * L_DIM); \
        float4* d4_ = (float4*)(stg + ((i_) & 1) * 1024);                       \
        _Pragma("unroll")                                                       \
        for (int k_ = 0; k_ < 8; k_++)                                          \
            __pipeline_memcpy_async(&d4_[lane + 32 * k_], &s4_[lane + 32 * k_], 16); \
    } while (0)

    if (n > 0) { ISSUE_CHUNK(0); }
    __pipeline_commit();

    for (int i = 0; i < n; i++) {
        if (i + 1 < n) { ISSUE_CHUNK(i + 1); }
        __pipeline_commit();            // always commit -> constant wait count
        __pipeline_wait_prior(1);       // chunk i ready; chunk i+1 in flight

        const int c = c0 + i;

        // ---- consume chunk: row stats ----
        {
            const float4* d4 = (const float4*)(stg + (i & 1) * 1024);
            float sa = 0.f, sb = 0.f, qa = 0.f, qb = 0.f;
            float mx = -FLT_MAX, mn = FLT_MAX;
            #pragma unroll
            for (int k = 0; k < 8; k++) {
                float4 v = d4[lane + 32 * k];
                if (k & 1) { sb += (v.x + v.y) + (v.z + v.w);
                             qb += (v.x * v.x + v.y * v.y) + (v.z * v.z + v.w * v.w); }
                else       { sa += (v.x + v.y) + (v.z + v.w);
                             qa += (v.x * v.x + v.y * v.y) + (v.z * v.z + v.w * v.w); }
                mx = fmaxf(mx, fmaxf(fmaxf(v.x, v.y), fmaxf(v.z, v.w)));
                mn = fminf(mn, fminf(fminf(v.x, v.y), fminf(v.z, v.w)));
            }
            float s = sa + sb, q = qa + qb;
            #pragma unroll
            for (int off = 16; off > 0; off >>= 1) {
                s  += __shfl_xor_sync(0xffffffffu, s, off);
                q  += __shfl_xor_sync(0xffffffffu, q, off);
                mx  = fmaxf(mx, __shfl_xor_sync(0xffffffffu, mx, off));
                mn  = fminf(mn, __shfl_xor_sync(0xffffffffu, mn, off));
            }
            if (lane == 0) {
                const int lr = (c >> 1) & 7;      // local row in group
                const int t  = (c & 1) * 4;
                rs[w][lr * 8 + t + 0] = s;
                rs[w][lr * 8 + t + 1] = sqrtf(fmaxf(0.f, (q - s * s * invL) * invN1));
                rs[w][lr * 8 + t + 2] = mx;
                rs[w][lr * 8 + t + 3] = mn;
            }
        }

        // ---- group complete? run inline MLP (next chunk still in flight) ----
        if ((c & 15) == 15) {
            __syncwarp();                         // rs[w] visible to all lanes
            const long long row0 = (long long)(c >> 4) * 8;

            float acc = 0.f;
            #pragma unroll
            for (int wi = 0; wi < 7; wi++) {
                int s, ws, r0;
                float wgt;
                if (wi == 0)      { s = 2; ws = 8; r0 = 0;            wgt = w2g; }
                else if (wi < 3)  { s = 1; ws = 4; r0 = (wi - 1) * 4; wgt = w1g; }
                else              { s = 0; ws = 2; r0 = (wi - 3) * 2; wgt = w0;  }

                const float invws = 1.0f / (float)ws;

                float g[8];
                {
                    float sm1 = 0.f, sd1 = 0.f, sx1 = 0.f, sn1 = 0.f;
                    float sm2 = 0.f, sd2 = 0.f, sx2 = 0.f, sn2 = 0.f;
                    #pragma unroll
                    for (int r = 0; r < 8; r++) {
                        if (r >= r0 && r < r0 + ws) {
                            sm1 += rs[w][r * 8 + 0]; sd1 += rs[w][r * 8 + 1];
                            sx1 += rs[w][r * 8 + 2]; sn1 += rs[w][r * 8 + 3];
                            sm2 += rs[w][r * 8 + 4]; sd2 += rs[w][r * 8 + 5];
                            sx2 += rs[w][r * 8 + 6]; sn2 += rs[w][r * 8 + 7];
                        }
                    }
                    g[0] = sm1 * invL * invws; g[1] = sd1 * invws;
                    g[2] = sx1 * invws;        g[3] = sn1 * invws;
                    g[4] = sm2 * invL * invws; g[5] = sd2 * invws;
                    g[6] = sx2 * invws;        g[7] = sn2 * invws;
                }

                float h1;
                {
                    float v = shB1[s][lane];
                    #pragma unroll
                    for (int f = 0; f < 8; f++) v = fmaf(shW1T[s][f][lane], g[f], v);
                    h1 = fmaxf(v, 0.f);
                }
                float h2;
                {
                    const int oo = lane & 15;
                    float v = shB2[s][oo];
                    #pragma unroll
                    for (int f = 0; f < 32; f++)
                        v = fmaf(shW2T[s][f][oo], __shfl_sync(0xffffffffu, h1, f), v);
                    h2 = fmaxf(v, 0.f);
                }
                {
                    float part = (lane < 16) ? shW3[s][lane] * h2 : 0.f;
                    #pragma unroll
                    for (int off = 16; off > 0; off >>= 1)
                        part += __shfl_xor_sync(0xffffffffu, part, off);
                    float z = __shfl_sync(0xffffffffu, part, 0) + shB3[s];
                    float alpha = 1.0f / (1.0f + __expf(-z));
                    if (lane >= r0 && lane < r0 + ws)
                        acc = fmaf(wgt, alpha, acc);
                }
            }

            if (lane < 8)
                out[row0 + lane] = acc;
        }
    }
    #undef ISSUE_CHUNK
}

extern "C" void kernel_launch(void* const* d_in, const int* in_sizes, int n_in,
                              void* d_out, int out_size) {
    const float* a1 = (const float*)d_in[0];
    const float* a2 = (const float*)d_in[1];
    const float* W1 = (const float*)d_in[2];
    const float* b1 = (const float*)d_in[3];
    const float* W2 = (const float*)d_in[4];
    const float* b2 = (const float*)d_in[5];
    const float* W3 = (const float*)d_in[6];
    const float* b3 = (const float*)d_in[7];
    const float* sw = (const float*)d_in[8];
    float* out = (float*)d_out;

    const int dyn_smem = 8 * 2 * 1024 * (int)sizeof(float);   // 64KB
    cudaFuncSetAttribute(msdfg_kernel,
                         cudaFuncAttributeMaxDynamicSharedMemorySize, dyn_smem);

    msdfg_kernel<<<GRID_A, 256, dyn_smem>>>(a1, a2, W1, b1, W2, b2, W3, b3, sw, out);
}